// round 8
// baseline (speedup 1.0000x reference)
#include <cuda_runtime.h>
#include <math.h>

#define BATCH 64
#define IMH 512
#define IMW 512
#define NC 64
#define NORI 9
#define NB 63
#define OUT_PER_B (NB*NB*2*2*NORI)   // 142884
#define NPOS (NB*NB)                 // 3969

// Transposed cell histogram scratch: [B][9][NC][NC] = 9.4 MB (L2-resident)
__device__ float g_hist[(size_t)BATCH * NORI * NC * NC];

__device__ __forceinline__ float fsqrt_approx(float v) {
    float r;
    asm("sqrt.approx.f32 %0, %1;" : "=f"(r) : "f"(v));
    return r;
}

// ---------------------------------------------------------------------------
// Kernel 1: gray -> gradients -> orientation cumsum -> 8x8 cell histograms
// Tile = 32x64 pixels (4x8 cells), 256 threads, thread = 2x4 pixel patch.
// 6 CTAs/SM (48 warps) via reg cap; trimmed live state (20-elem patch);
// shared-product boundary tests (12 ops/px vs 16).
// ---------------------------------------------------------------------------
__global__ __launch_bounds__(256, 6) void hog_cells_kernel(const float* __restrict__ x)
{
    __shared__ float sm[34][68];        // 34x66 gray halo tile, padded stride
    __shared__ float shist[NORI][32];   // per-cell hist staging

    const int bx = blockIdx.x;          // 0..7   (64-px cols)
    const int by = blockIdx.y;          // 0..15  (32-px rows)
    const int b  = blockIdx.z;
    const int tid = threadIdx.x;
    const int oy = by * 32;
    const int ox = bx * 64;

    // ---- interior 32x64 gray: 2x (3x LDG.128 -> 4 pixels) ----
    const int row0 = tid >> 4;              // 0..15
    const int g0   = tid & 15;
    const size_t offA = ((size_t)((b * IMH) + oy + row0) * IMW + ox + g0 * 4) * 3;
    const size_t offB = ((size_t)((b * IMH) + oy + row0 + 16) * IMW + ox + g0 * 4) * 3;
    const float4* pA = reinterpret_cast<const float4*>(x + offA);
    const float4* pB = reinterpret_cast<const float4*>(x + offB);

    // ---- halo ring (196 px): unconditional load, predicated store ----
    const int ht = (tid < 196) ? tid : 195;
    int lr, lc;
    if (ht < 66)       { lr = 0;        lc = ht;       }
    else if (ht < 132) { lr = 33;       lc = ht - 66;  }
    else if (ht < 164) { lr = ht - 131; lc = 0;        }
    else               { lr = ht - 163; lc = 65;       }
    int hh = oy - 1 + lr;
    int hw = ox - 1 + lc;
    hh = (hh < 0) ? 1 : ((hh > IMH - 1) ? IMH - 2 : hh);
    hw = (hw < 0) ? 1 : ((hw > IMW - 1) ? IMW - 2 : hw);
    const float* hp = x + ((size_t)(b * IMH + hh) * IMW + hw) * 3;

    // issue all loads back-to-back
    const float4 a0 = pA[0], a1 = pA[1], a2 = pA[2];
    const float4 b0 = pB[0], b1 = pB[1], b2 = pB[2];
    const float  h0 = hp[0], h1 = hp[1], h2 = hp[2];

    {
        float* d = &sm[row0 + 1][g0 * 4 + 1];
        d[0] = 0.2125f * a0.x + 0.7154f * a0.y + 0.0721f * a0.z;
        d[1] = 0.2125f * a0.w + 0.7154f * a1.x + 0.0721f * a1.y;
        d[2] = 0.2125f * a1.z + 0.7154f * a1.w + 0.0721f * a2.x;
        d[3] = 0.2125f * a2.y + 0.7154f * a2.z + 0.0721f * a2.w;
        float* e = &sm[row0 + 17][g0 * 4 + 1];
        e[0] = 0.2125f * b0.x + 0.7154f * b0.y + 0.0721f * b0.z;
        e[1] = 0.2125f * b0.w + 0.7154f * b1.x + 0.0721f * b1.y;
        e[2] = 0.2125f * b1.z + 0.7154f * b1.w + 0.0721f * b2.x;
        e[3] = 0.2125f * b2.y + 0.7154f * b2.z + 0.0721f * b2.w;
    }
    if (tid < 196)
        sm[lr][lc] = 0.2125f * h0 + 0.7154f * h1 + 0.0721f * h2;
    __syncthreads();

    // ---- 2x4 pixel patch per thread (8 threads per 8x8 cell) ----
    const int cell = tid >> 3;          // 0..31
    const int sub  = tid & 7;
    const int py  = (cell >> 3) * 8 + (sub >> 1) * 2;   // 2-row band base
    const int px0 = (cell & 7) * 8 + (sub & 1) * 4;     // multiple of 4

    // Trimmed patch: rows py+0 / py+3 need cols 1..4; rows py+1/py+2 need 0..5.
    float t0a, t0b, t0c, t0d;                 // row py+0, cols 1..4
    float m1[6], m2[6];                       // rows py+1, py+2, cols 0..5
    float t3a, t3b, t3c, t3d;                 // row py+3, cols 1..4
    {
        const float4 r0 = *reinterpret_cast<const float4*>(&sm[py][px0]);
        const float2 r0e = *reinterpret_cast<const float2*>(&sm[py][px0 + 4]);
        t0a = r0.y; t0b = r0.z; t0c = r0.w; t0d = r0e.x;
        const float4 r1 = *reinterpret_cast<const float4*>(&sm[py + 1][px0]);
        const float2 r1e = *reinterpret_cast<const float2*>(&sm[py + 1][px0 + 4]);
        m1[0] = r1.x; m1[1] = r1.y; m1[2] = r1.z; m1[3] = r1.w; m1[4] = r1e.x; m1[5] = r1e.y;
        const float4 r2 = *reinterpret_cast<const float4*>(&sm[py + 2][px0]);
        const float2 r2e = *reinterpret_cast<const float2*>(&sm[py + 2][px0 + 4]);
        m2[0] = r2.x; m2[1] = r2.y; m2[2] = r2.z; m2[3] = r2.w; m2[4] = r2e.x; m2[5] = r2e.y;
        const float4 r3 = *reinterpret_cast<const float4*>(&sm[py + 3][px0]);
        const float2 r3e = *reinterpret_cast<const float2*>(&sm[py + 3][px0 + 4]);
        t3a = r3.y; t3b = r3.z; t3c = r3.w; t3d = r3e.x;
    }

    float c[NORI];
#pragma unroll
    for (int o = 0; o < NORI; o++) c[o] = 0.0f;

#pragma unroll
    for (int dy = 0; dy < 2; dy++) {
#pragma unroll
        for (int dx = 0; dx < 4; dx++) {
            float top, bot, lef, rig;
            if (dy == 0) {
                top = (dx == 0) ? t0a : (dx == 1) ? t0b : (dx == 2) ? t0c : t0d;
                bot = m2[dx + 1];
                lef = m1[dx]; rig = m1[dx + 2];
            } else {
                top = m1[dx + 1];
                bot = (dx == 0) ? t3a : (dx == 1) ? t3b : (dx == 2) ? t3c : t3d;
                lef = m2[dx]; rig = m2[dx + 2];
            }
            const float gr = bot - top;
            const float gc = rig - lef;
            const float mag = fsqrt_approx(gr * gr + gc * gc);

            // canonicalize to theta in [0,180)
            const bool flip = (gr < 0.0f) || (gr == 0.0f && gc < 0.0f);
            const float yy = flip ? -gr : gr;
            const float xx = flip ? -gc : gc;

            // shared products: xa_k = xx*sin(20k); s_k = xa_k -/+ yy*cos(20k)
            const float xa1 = xx * 0.3420201433f;
            const float xa2 = xx * 0.6427876097f;
            const float xa3 = xx * 0.8660254038f;
            const float xa4 = xx * 0.9848077530f;
            const float s1 = xa1 - yy * 0.9396926208f;
            const float s8 = xa1 + yy * 0.9396926208f;
            const float s2 = xa2 - yy * 0.7660444431f;
            const float s7 = xa2 + yy * 0.7660444431f;
            const float s3 = xa3 - yy * 0.5000000000f;
            const float s6 = xa3 + yy * 0.5000000000f;
            const float s4 = xa4 - yy * 0.1736481777f;
            const float s5 = xa4 + yy * 0.1736481777f;

            c[0] += mag;
            if (s1 < 0.0f) c[1] += mag;
            if (s2 < 0.0f) c[2] += mag;
            if (s3 < 0.0f) c[3] += mag;
            if (s4 < 0.0f) c[4] += mag;
            if (s5 < 0.0f) c[5] += mag;
            if (s6 < 0.0f) c[6] += mag;
            if (s7 < 0.0f) c[7] += mag;
            if (s8 < 0.0f) c[8] += mag;
        }
    }

    // reduce 8 patch threads per cell (consecutive lanes)
#pragma unroll
    for (int o = 0; o < NORI; o++) {
        c[o] += __shfl_xor_sync(0xffffffffu, c[o], 1);
        c[o] += __shfl_xor_sync(0xffffffffu, c[o], 2);
        c[o] += __shfl_xor_sync(0xffffffffu, c[o], 4);
    }

    if (sub == 0) {
#pragma unroll
        for (int o = 0; o < NORI - 1; o++)
            shist[o][cell] = (c[o] - c[o + 1]) * 0.015625f;
        shist[NORI - 1][cell] = c[NORI - 1] * 0.015625f;
    }
    __syncthreads();

    // ---- transposed global store: g_hist[b][o][cellY][cellX] ----
    const size_t base = (size_t)b * NORI * NC * NC;
    for (int i = tid; i < NORI * 32; i += 256) {
        const int o   = i >> 5;
        const int cl  = i & 31;
        g_hist[base + (size_t)o * (NC * NC) + (by * 4 + (cl >> 3)) * NC + (bx * 8 + (cl & 7))]
            = shist[o][cl];
    }
}

// ---------------------------------------------------------------------------
// Kernel 2: 4 threads per block position (1 cell each), shfl-reduced norms,
// conflict-free smem staging, float4 coalesced out.  (unchanged)
// ---------------------------------------------------------------------------
__global__ __launch_bounds__(256) void hog_blocks_kernel(float* __restrict__ out)
{
    __shared__ float buf[64 * 36];

    const int b   = blockIdx.y;
    const int p0  = blockIdx.x * 64;
    const int tid = threadIdx.x;

    const int lp = tid >> 2;
    const int q  = tid & 3;
    const int p  = p0 + lp;
    const bool valid = (p < NPOS);
    const int pc = valid ? p : NPOS - 1;
    const int rp = pc / NB;
    const int cp = pc - rp * NB;
    const int dr = q >> 1;
    const int dc = q & 1;

    const float* hp = g_hist + (size_t)b * NORI * NC * NC + (rp + dr) * NC + (cp + dc);

    float v[NORI];
    float ss = 0.25e-10f;
#pragma unroll
    for (int o = 0; o < NORI; o++) {
        const float t = hp[(size_t)o * (NC * NC)];
        v[o] = t;
        ss += t * t;
    }
    ss += __shfl_xor_sync(0xffffffffu, ss, 1);
    ss += __shfl_xor_sync(0xffffffffu, ss, 2);

    const float n1 = rsqrtf(ss);
    float ss2 = 0.25e-10f;
#pragma unroll
    for (int o = 0; o < NORI; o++) {
        const float t = fminf(v[o] * n1, 0.2f);
        v[o] = t;
        ss2 += t * t;
    }
    ss2 += __shfl_xor_sync(0xffffffffu, ss2, 1);
    ss2 += __shfl_xor_sync(0xffffffffu, ss2, 2);

    const float n2 = rsqrtf(ss2);
    if (valid) {
        float* d = &buf[lp * 36 + q * NORI];
#pragma unroll
        for (int o = 0; o < NORI; o++)
            d[o] = v[o] * n2;
    }
    __syncthreads();

    const int npos = min(64, NPOS - p0);
    const int n4 = npos * 9;
    const float4* s4 = reinterpret_cast<const float4*>(buf);
    float4* o4 = reinterpret_cast<float4*>(out + (size_t)b * OUT_PER_B + (size_t)p0 * 36);
    for (int i = tid; i < n4; i += 256)
        o4[i] = s4[i];
}

extern "C" void kernel_launch(void* const* d_in, const int* in_sizes, int n_in,
                              void* d_out, int out_size)
{
    const float* x = (const float*)d_in[0];
    float* out = (float*)d_out;

    dim3 g1(IMW / 64, IMH / 32, BATCH);          // (8, 16, 64) = 8192 CTAs
    hog_cells_kernel<<<g1, 256>>>(x);

    dim3 g2((NPOS + 63) / 64, BATCH);            // (63, 64)
    hog_blocks_kernel<<<g2, 256>>>(out);
}

// round 9
// speedup vs baseline: 1.0930x; 1.0930x over previous
#include <cuda_runtime.h>
#include <math.h>

#define BATCH 64
#define IMH 512
#define IMW 512
#define NC 64
#define NORI 9
#define NB 63
#define OUT_PER_B (NB*NB*2*2*NORI)   // 142884
#define NPOS (NB*NB)                 // 3969

// Transposed cell histogram scratch: [B][9][NC][NC] = 9.4 MB (L2-resident)
__device__ float g_hist[(size_t)BATCH * NORI * NC * NC];

__device__ __forceinline__ float fsqrt_approx(float v) {
    float r;
    asm("sqrt.approx.f32 %0, %1;" : "=f"(r) : "f"(v));
    return r;
}

// ---------------------------------------------------------------------------
// Kernel 1: gray -> gradients -> orientation cumsum -> 8x8 cell histograms
// Tile = 32x64 pixels (4x8 cells), 256 threads, thread = 2x4 pixel patch.
// 5 CTAs/SM (40 warps, 51 regs, no spill); front-batched loads for MLP;
// shared-product boundary tests (12 ops/px vs 16).
// ---------------------------------------------------------------------------
__global__ __launch_bounds__(256, 5) void hog_cells_kernel(const float* __restrict__ x)
{
    __shared__ float sm[34][68];        // 34x66 gray halo tile, padded stride
    __shared__ float shist[NORI][32];   // per-cell hist staging

    const int bx = blockIdx.x;          // 0..7   (64-px cols)
    const int by = blockIdx.y;          // 0..15  (32-px rows)
    const int b  = blockIdx.z;
    const int tid = threadIdx.x;
    const int oy = by * 32;
    const int ox = bx * 64;

    // ---- interior 32x64 gray: 2x (3x LDG.128 -> 4 pixels) ----
    const int row0 = tid >> 4;              // 0..15
    const int g0   = tid & 15;
    const size_t offA = ((size_t)((b * IMH) + oy + row0) * IMW + ox + g0 * 4) * 3;
    const size_t offB = ((size_t)((b * IMH) + oy + row0 + 16) * IMW + ox + g0 * 4) * 3;
    const float4* pA = reinterpret_cast<const float4*>(x + offA);
    const float4* pB = reinterpret_cast<const float4*>(x + offB);

    // ---- halo ring (196 px): unconditional load, predicated store ----
    const int ht = (tid < 196) ? tid : 195;
    int lr, lc;
    if (ht < 66)       { lr = 0;        lc = ht;       }
    else if (ht < 132) { lr = 33;       lc = ht - 66;  }
    else if (ht < 164) { lr = ht - 131; lc = 0;        }
    else               { lr = ht - 163; lc = 65;       }
    int hh = oy - 1 + lr;
    int hw = ox - 1 + lc;
    hh = (hh < 0) ? 1 : ((hh > IMH - 1) ? IMH - 2 : hh);
    hw = (hw < 0) ? 1 : ((hw > IMW - 1) ? IMW - 2 : hw);
    const float* hp = x + ((size_t)(b * IMH + hh) * IMW + hw) * 3;

    // issue all loads back-to-back
    const float4 a0 = pA[0], a1 = pA[1], a2 = pA[2];
    const float4 b0 = pB[0], b1 = pB[1], b2 = pB[2];
    const float  h0 = hp[0], h1 = hp[1], h2 = hp[2];

    {
        float* d = &sm[row0 + 1][g0 * 4 + 1];
        d[0] = 0.2125f * a0.x + 0.7154f * a0.y + 0.0721f * a0.z;
        d[1] = 0.2125f * a0.w + 0.7154f * a1.x + 0.0721f * a1.y;
        d[2] = 0.2125f * a1.z + 0.7154f * a1.w + 0.0721f * a2.x;
        d[3] = 0.2125f * a2.y + 0.7154f * a2.z + 0.0721f * a2.w;
        float* e = &sm[row0 + 17][g0 * 4 + 1];
        e[0] = 0.2125f * b0.x + 0.7154f * b0.y + 0.0721f * b0.z;
        e[1] = 0.2125f * b0.w + 0.7154f * b1.x + 0.0721f * b1.y;
        e[2] = 0.2125f * b1.z + 0.7154f * b1.w + 0.0721f * b2.x;
        e[3] = 0.2125f * b2.y + 0.7154f * b2.z + 0.0721f * b2.w;
    }
    if (tid < 196)
        sm[lr][lc] = 0.2125f * h0 + 0.7154f * h1 + 0.0721f * h2;
    __syncthreads();

    // ---- 2x4 pixel patch per thread (8 threads per 8x8 cell) ----
    const int cell = tid >> 3;          // 0..31  (4 rows x 8 cols of cells)
    const int sub  = tid & 7;
    const int py0 = (cell >> 3) * 8 + (sub >> 1) * 2;   // 2-row band base
    const int px0 = (cell & 7) * 8 + (sub & 1) * 4;     // multiple of 4

    // 4x6 gray patch via 4x (LDS.128 + LDS.64)  -- proven R6 layout
    float P[4][6];
#pragma unroll
    for (int r = 0; r < 4; r++) {
        const float4 a = *reinterpret_cast<const float4*>(&sm[py0 + r][px0]);
        const float2 e = *reinterpret_cast<const float2*>(&sm[py0 + r][px0 + 4]);
        P[r][0] = a.x; P[r][1] = a.y; P[r][2] = a.z; P[r][3] = a.w;
        P[r][4] = e.x; P[r][5] = e.y;
    }

    float c[NORI];
#pragma unroll
    for (int o = 0; o < NORI; o++) c[o] = 0.0f;

#pragma unroll
    for (int dy = 0; dy < 2; dy++) {
#pragma unroll
        for (int dx = 0; dx < 4; dx++) {
            const float gr = P[dy + 2][dx + 1] - P[dy][dx + 1];
            const float gc = P[dy + 1][dx + 2] - P[dy + 1][dx];
            const float mag = fsqrt_approx(gr * gr + gc * gc);

            // canonicalize to theta in [0,180)
            const bool flip = (gr < 0.0f) || (gr == 0.0f && gc < 0.0f);
            const float yy = flip ? -gr : gr;
            const float xx = flip ? -gc : gc;

            // shared products: xa_k = xx*sin(20k); s_k = xa_k -/+ yy*cos(20k)
            const float xa1 = xx * 0.3420201433f;
            const float xa2 = xx * 0.6427876097f;
            const float xa3 = xx * 0.8660254038f;
            const float xa4 = xx * 0.9848077530f;
            const float s1 = xa1 - yy * 0.9396926208f;
            const float s8 = xa1 + yy * 0.9396926208f;
            const float s2 = xa2 - yy * 0.7660444431f;
            const float s7 = xa2 + yy * 0.7660444431f;
            const float s3 = xa3 - yy * 0.5000000000f;
            const float s6 = xa3 + yy * 0.5000000000f;
            const float s4 = xa4 - yy * 0.1736481777f;
            const float s5 = xa4 + yy * 0.1736481777f;

            c[0] += mag;
            if (s1 < 0.0f) c[1] += mag;
            if (s2 < 0.0f) c[2] += mag;
            if (s3 < 0.0f) c[3] += mag;
            if (s4 < 0.0f) c[4] += mag;
            if (s5 < 0.0f) c[5] += mag;
            if (s6 < 0.0f) c[6] += mag;
            if (s7 < 0.0f) c[7] += mag;
            if (s8 < 0.0f) c[8] += mag;
        }
    }

    // reduce 8 patch threads per cell (consecutive lanes)
#pragma unroll
    for (int o = 0; o < NORI; o++) {
        c[o] += __shfl_xor_sync(0xffffffffu, c[o], 1);
        c[o] += __shfl_xor_sync(0xffffffffu, c[o], 2);
        c[o] += __shfl_xor_sync(0xffffffffu, c[o], 4);
    }

    if (sub == 0) {
#pragma unroll
        for (int o = 0; o < NORI - 1; o++)
            shist[o][cell] = (c[o] - c[o + 1]) * 0.015625f;   // hist[o] = c_o - c_{o+1}
        shist[NORI - 1][cell] = c[NORI - 1] * 0.015625f;
    }
    __syncthreads();

    // ---- transposed global store: g_hist[b][o][cellY][cellX] ----
    const size_t base = (size_t)b * NORI * NC * NC;
    for (int i = tid; i < NORI * 32; i += 256) {
        const int o   = i >> 5;
        const int cl  = i & 31;
        g_hist[base + (size_t)o * (NC * NC) + (by * 4 + (cl >> 3)) * NC + (bx * 8 + (cl & 7))]
            = shist[o][cl];
    }
}

// ---------------------------------------------------------------------------
// Kernel 2: 4 threads per block position (1 cell each), shfl-reduced norms,
// conflict-free smem staging, float4 coalesced out.  (unchanged, proven)
// ---------------------------------------------------------------------------
__global__ __launch_bounds__(256) void hog_blocks_kernel(float* __restrict__ out)
{
    __shared__ float buf[64 * 36];

    const int b   = blockIdx.y;
    const int p0  = blockIdx.x * 64;
    const int tid = threadIdx.x;

    const int lp = tid >> 2;
    const int q  = tid & 3;
    const int p  = p0 + lp;
    const bool valid = (p < NPOS);
    const int pc = valid ? p : NPOS - 1;
    const int rp = pc / NB;
    const int cp = pc - rp * NB;
    const int dr = q >> 1;
    const int dc = q & 1;

    const float* hp = g_hist + (size_t)b * NORI * NC * NC + (rp + dr) * NC + (cp + dc);

    float v[NORI];
    float ss = 0.25e-10f;
#pragma unroll
    for (int o = 0; o < NORI; o++) {
        const float t = hp[(size_t)o * (NC * NC)];
        v[o] = t;
        ss += t * t;
    }
    ss += __shfl_xor_sync(0xffffffffu, ss, 1);
    ss += __shfl_xor_sync(0xffffffffu, ss, 2);

    const float n1 = rsqrtf(ss);
    float ss2 = 0.25e-10f;
#pragma unroll
    for (int o = 0; o < NORI; o++) {
        const float t = fminf(v[o] * n1, 0.2f);
        v[o] = t;
        ss2 += t * t;
    }
    ss2 += __shfl_xor_sync(0xffffffffu, ss2, 1);
    ss2 += __shfl_xor_sync(0xffffffffu, ss2, 2);

    const float n2 = rsqrtf(ss2);
    if (valid) {
        float* d = &buf[lp * 36 + q * NORI];
#pragma unroll
        for (int o = 0; o < NORI; o++)
            d[o] = v[o] * n2;
    }
    __syncthreads();

    const int npos = min(64, NPOS - p0);
    const int n4 = npos * 9;
    const float4* s4 = reinterpret_cast<const float4*>(buf);
    float4* o4 = reinterpret_cast<float4*>(out + (size_t)b * OUT_PER_B + (size_t)p0 * 36);
    for (int i = tid; i < n4; i += 256)
        o4[i] = s4[i];
}

extern "C" void kernel_launch(void* const* d_in, const int* in_sizes, int n_in,
                              void* d_out, int out_size)
{
    const float* x = (const float*)d_in[0];
    float* out = (float*)d_out;

    dim3 g1(IMW / 64, IMH / 32, BATCH);          // (8, 16, 64) = 8192 CTAs
    hog_cells_kernel<<<g1, 256>>>(x);

    dim3 g2((NPOS + 63) / 64, BATCH);            // (63, 64)
    hog_blocks_kernel<<<g2, 256>>>(out);
}